// round 2
// baseline (speedup 1.0000x reference)
#include <cuda_runtime.h>
#include <math.h>

#define N_ROWS 16384
#define DDIM   4096
#define NEXP   256
#define KTOP   6

#define BM 128
#define BN 64
#define BK 16
#define TM 8
#define TN 8
#define TX 8    // BN/TN
#define TY 16   // BM/TM
#define NTHREADS 128
#define KCHUNK 64   // fold chunk accumulators into master every 64 k-steps

// 16 MB scratch for the raw gate scores [N, E]
__device__ float g_scores[(size_t)N_ROWS * NEXP];

// ---------------------------------------------------------------------------
// GEMM: C[N,E] = A[N,D] * B[E,D]^T (both K-major), fp32, packed fma.rn.f32x2.
// Two-level accumulation: fp32 chunk accumulators over KCHUNK k-steps are
// folded into a separate fp32 master, cutting accumulation error ~4x vs a
// single sequential chain (deviation from exact ~4e-7 abs) so the top-k
// decision tracks the exact scores as closely as fp32 output allows.
// ---------------------------------------------------------------------------
__global__ __launch_bounds__(NTHREADS, 1) void gemm_f32x2(
    const float* __restrict__ A, const float* __restrict__ B) {
    __shared__ float As[BK][BM];         // As[k][m]
    __shared__ float Bsd[BK][BN * 2];    // Bsd[k][2n] = Bsd[k][2n+1] = B[n][k]

    const int tid = threadIdx.x;
    const int tx = tid % TX;             // 0..7   (col group of 8)
    const int ty = tid / TX;             // 0..15  (row group of 8)
    const int mBase = blockIdx.y * BM;
    const int nBase = blockIdx.x * BN;

    unsigned long long acc[TM / 2][TN];   // chunk accumulators (f32x2 pairs)
    unsigned long long msum[TM / 2][TN];  // master accumulators
#pragma unroll
    for (int i = 0; i < TM / 2; i++)
#pragma unroll
        for (int j = 0; j < TN; j++) { acc[i][j] = 0ULL; msum[i][j] = 0ULL; }

    for (int k0 = 0; k0 < DDIM; k0 += KCHUNK) {
#pragma unroll 1
        for (int kb = 0; kb < KCHUNK / BK; kb++) {
            const int kk = k0 + kb * BK;
            // ---- A tile: thread tid owns row (mBase+tid), 4 float4 along k
#pragma unroll
            for (int l = 0; l < 4; l++) {
                float4 v = *reinterpret_cast<const float4*>(
                    &A[(size_t)(mBase + tid) * DDIM + kk + l * 4]);
                As[l * 4 + 0][tid] = v.x;
                As[l * 4 + 1][tid] = v.y;
                As[l * 4 + 2][tid] = v.z;
                As[l * 4 + 3][tid] = v.w;
            }
            // ---- B tile (duplicated): n = tid>>1, kq = 2*(tid&1)+l
#pragma unroll
            for (int l = 0; l < 2; l++) {
                int n  = tid >> 1;
                int kq = 2 * (tid & 1) + l;
                float4 v = *reinterpret_cast<const float4*>(
                    &B[(size_t)(nBase + n) * DDIM + kk + kq * 4]);
                Bsd[kq * 4 + 0][2 * n] = v.x; Bsd[kq * 4 + 0][2 * n + 1] = v.x;
                Bsd[kq * 4 + 1][2 * n] = v.y; Bsd[kq * 4 + 1][2 * n + 1] = v.y;
                Bsd[kq * 4 + 2][2 * n] = v.z; Bsd[kq * 4 + 2][2 * n + 1] = v.z;
                Bsd[kq * 4 + 3][2 * n] = v.w; Bsd[kq * 4 + 3][2 * n + 1] = v.w;
            }
            __syncthreads();

#pragma unroll
            for (int k = 0; k < BK; k++) {
                unsigned long long a2[TM / 2], b2[TN];
#pragma unroll
                for (int i = 0; i < TM / 2; i++)
                    a2[i] = *reinterpret_cast<const unsigned long long*>(
                        &As[k][ty * TM + 2 * i]);
#pragma unroll
                for (int j = 0; j < TN; j++)
                    b2[j] = *reinterpret_cast<const unsigned long long*>(
                        &Bsd[k][(tx * TN + j) * 2]);
#pragma unroll
                for (int i = 0; i < TM / 2; i++)
#pragma unroll
                    for (int j = 0; j < TN; j++)
                        asm("fma.rn.f32x2 %0, %1, %2, %0;"
                            : "+l"(acc[i][j]) : "l"(a2[i]), "l"(b2[j]));
            }
            __syncthreads();
        }
        // ---- fold chunk accumulators into master, reset chunk
#pragma unroll
        for (int i = 0; i < TM / 2; i++)
#pragma unroll
            for (int j = 0; j < TN; j++) {
                asm("add.rn.f32x2 %0, %0, %1;"
                    : "+l"(msum[i][j]) : "l"(acc[i][j]));
                acc[i][j] = 0ULL;
            }
    }

    // ---- epilogue: msum[i][j] = rows (ty*8+2i, ty*8+2i+1), col tx*8+j
#pragma unroll
    for (int i = 0; i < TM / 2; i++) {
#pragma unroll
        for (int j = 0; j < TN; j++) {
            float lo = __uint_as_float((unsigned)(msum[i][j] & 0xFFFFFFFFu));
            float hi = __uint_as_float((unsigned)(msum[i][j] >> 32));
            int m = mBase + ty * TM + 2 * i;
            int n = nBase + tx * TN + j;
            g_scores[(size_t)m * NEXP + n]       = lo;
            g_scores[(size_t)(m + 1) * NEXP + n] = hi;
        }
    }
}

// ---------------------------------------------------------------------------
// Per-row epilogue: sqrt(softplus), +bias, stable top-6 (lower index wins
// ties, matching jax.lax.top_k), renormalize selected original scores * 1.5.
// One block of 256 threads per row (one thread per expert). fp32 transcendental
// formula matches the XLA lowering (max(z,0)+log1p(exp(-|z|))) via libdevice.
// ---------------------------------------------------------------------------
__global__ __launch_bounds__(NEXP) void topk_kernel(
    const float* __restrict__ bias, float* __restrict__ out) {
    const int row = blockIdx.x;
    const int e   = threadIdx.x;

    __shared__ float s_orig[NEXP];
    __shared__ unsigned long long s_key[NEXP];
    __shared__ int   s_sel[KTOP];
    __shared__ float s_w[KTOP];

    float z  = g_scores[(size_t)row * NEXP + e];
    float sp = fmaxf(z, 0.0f) + log1pf(expf(-fabsf(z)));
    float orig   = sqrtf(sp);
    float biased = orig + bias[e];
    s_orig[e] = orig;

    // order-preserving uint encoding of float; ties broken by lower index
    unsigned ub = __float_as_uint(biased);
    ub = (ub & 0x80000000u) ? ~ub : (ub | 0x80000000u);
    unsigned long long mykey =
        ((unsigned long long)ub << 32) | (unsigned)(NEXP - 1 - e);

    bool taken = false;
    for (int r = 0; r < KTOP; r++) {
        s_key[e] = taken ? 0ULL : mykey;
        __syncthreads();
#pragma unroll
        for (int s = NEXP / 2; s > 0; s >>= 1) {
            if (e < s) {
                unsigned long long o = s_key[e + s];
                if (o > s_key[e]) s_key[e] = o;
            }
            __syncthreads();
        }
        int widx = NEXP - 1 - (int)(s_key[0] & 0xFFFFFFFFu);
        if (e == widx) taken = true;
        if (e == r) { s_sel[r] = widx; s_w[r] = s_orig[widx]; }
        __syncthreads();
    }

    if (e < KTOP) {
        float sum = 0.0f;
#pragma unroll
        for (int i = 0; i < KTOP; i++) sum += s_w[i];
        float w = (s_w[e] / sum) * 1.5f;
        out[(size_t)row * KTOP + e] = w;
        out[(size_t)N_ROWS * KTOP + (size_t)row * KTOP + e] = (float)s_sel[e];
    }
}

extern "C" void kernel_launch(void* const* d_in, const int* in_sizes, int n_in,
                              void* d_out, int out_size) {
    const float* x      = (const float*)d_in[0];   // [N, D]
    const float* weight = (const float*)d_in[1];   // [E, D]
    const float* bias   = (const float*)d_in[2];   // [E]
    float* out = (float*)d_out;

    dim3 grid(NEXP / BN, N_ROWS / BM);             // (4, 128)
    gemm_f32x2<<<grid, NTHREADS>>>(x, weight);
    topk_kernel<<<N_ROWS, NEXP>>>(bias, out);
}

// round 5
// speedup vs baseline: 4.1323x; 4.1323x over previous
#include <cuda_runtime.h>
#include <cuda_bf16.h>
#include <cstdint>
#include <math.h>

#define N_ROWS 16384
#define DDIM   4096
#define NEXP   256
#define KTOP   6

#define BM 64             // rows per CTA
#define BK 32             // k per stage (two k16 steps)
#define NIT (DDIM / BK)   // 128
#define NTHREADS 256      // 8 warps: 2 (m) x 4 (n), warp tile 32x64

// ---- smem layout (dynamic) ----
// [0,1024): bias; stages at 1024 + s*61440
// stage: A_h 4K | A_m 4K | A_l 4K | B_h 16K | B_m 16K | B_l 16K  = 60K
#define SM_BIAS    0
#define SM_STAGE   1024
#define STAGE_BYTES 61440
#define A_LVL_BYTES 4096
#define B_OFF      12288
#define B_LVL_BYTES 16384
#define SMEM_TOTAL (SM_STAGE + 2 * STAGE_BYTES)   // 123904

// scores overlay (after mainloop): stride 260 floats to dodge bank conflicts
#define SSTR 260
#define SM_SCORES  SM_STAGE
#define SM_PB (SM_SCORES + BM * SSTR * 4)     // 67584: partial biased [64][4][6]
#define SM_PO (SM_PB + BM * 4 * KTOP * 4)     // partial orig
#define SM_PI (SM_PO + BM * 4 * KTOP * 4)     // partial idx

// 6 MB pre-converted, pre-swizzled B: [it(128)][level(3)][n(256)][64B]
__device__ __align__(16) uint8_t g_bpre[(size_t)NIT * 3 * NEXP * 64];

// ---------------------------------------------------------------------------
static __device__ __forceinline__ uint32_t smem_u32(const void* p) {
    uint32_t a;
    asm("{ .reg .u64 t; cvta.to.shared.u64 t, %1; cvt.u32.u64 %0, t; }" : "=r"(a) : "l"(p));
    return a;
}

// proper shared-space 8-byte store (addr is a .shared u32 address)
static __device__ __forceinline__ void sts_u2(uint32_t addr, uint2 v) {
    asm volatile("st.shared.v2.b32 [%0], {%1, %2};"
                 :: "r"(addr), "r"(v.x), "r"(v.y) : "memory");
}

static __device__ __forceinline__ uint32_t pack_bf2(__nv_bfloat16 lo, __nv_bfloat16 hi) {
    return (uint32_t)__bfloat16_as_ushort(lo) | ((uint32_t)__bfloat16_as_ushort(hi) << 16);
}

// split fp32x4 into three bf16x4 levels (h, m, l), packed pairwise
static __device__ __forceinline__ void split3_f4(float4 v, uint2& h, uint2& m, uint2& l) {
    float in[4] = {v.x, v.y, v.z, v.w};
    __nv_bfloat16 bh[4], bm[4], bl[4];
#pragma unroll
    for (int i = 0; i < 4; i++) {
        float a = in[i];
        bh[i] = __float2bfloat16_rn(a);
        float r1 = a - __bfloat162float(bh[i]);
        bm[i] = __float2bfloat16_rn(r1);
        float r2 = r1 - __bfloat162float(bm[i]);
        bl[i] = __float2bfloat16_rn(r2);
    }
    h = make_uint2(pack_bf2(bh[0], bh[1]), pack_bf2(bh[2], bh[3]));
    m = make_uint2(pack_bf2(bm[0], bm[1]), pack_bf2(bm[2], bm[3]));
    l = make_uint2(pack_bf2(bl[0], bl[1]), pack_bf2(bl[2], bl[3]));
}

static __device__ __forceinline__ void ldsm4(uint32_t* r, uint32_t addr) {
    asm volatile("ldmatrix.sync.aligned.m8n8.x4.shared.b16 {%0,%1,%2,%3}, [%4];"
                 : "=r"(r[0]), "=r"(r[1]), "=r"(r[2]), "=r"(r[3]) : "r"(addr));
}

static __device__ __forceinline__ void mma_bf16(float* d, const uint32_t* a,
                                                uint32_t b0, uint32_t b1) {
    asm volatile(
        "mma.sync.aligned.m16n8k16.row.col.f32.bf16.bf16.f32 "
        "{%0,%1,%2,%3}, {%4,%5,%6,%7}, {%8,%9}, {%0,%1,%2,%3};"
        : "+f"(d[0]), "+f"(d[1]), "+f"(d[2]), "+f"(d[3])
        : "r"(a[0]), "r"(a[1]), "r"(a[2]), "r"(a[3]), "r"(b0), "r"(b1));
}

static __device__ __forceinline__ void cpasync16(uint32_t dst, const void* src) {
    asm volatile("cp.async.cg.shared.global [%0], [%1], 16;" :: "r"(dst), "l"(src) : "memory");
}

// 64B-row swizzle: physical 16B chunk = logical chunk ^ ((row>>1)&3)
static __device__ __forceinline__ uint32_t row64_addr(uint32_t base, int row, int lchunk) {
    return base + row * 64 + ((lchunk ^ ((row >> 1) & 3)) << 4);
}

// stable strict-> insertion into top-6 (earlier insert wins ties = lower index)
static __device__ __forceinline__ void ins6(float b, float o, int idx,
                                            float* tb, float* to_, int* ti) {
    if (b > tb[KTOP - 1]) {
        int p = KTOP - 1;
#pragma unroll
        for (int q = KTOP - 1; q > 0; q--) {
            if (b > tb[q - 1]) {
                tb[q] = tb[q - 1]; to_[q] = to_[q - 1]; ti[q] = ti[q - 1];
                p = q - 1;
            }
        }
        tb[p] = b; to_[p] = o; ti[p] = idx;
    }
}

// ---------------------------------------------------------------------------
// Pre-kernel: split B[256][4096] fp32 into 3 bf16 levels, stored as the exact
// per-iteration smem stage image (pre-swizzled 64B rows) for cp.async streaming.
// ---------------------------------------------------------------------------
__global__ __launch_bounds__(256) void preconvert_B(const float* __restrict__ B) {
    int t = blockIdx.x * 256 + threadIdx.x;        // one float4 each; 262144 total
    int n  = t >> 10;                              // row 0..255
    int g  = t & 1023;                             // float4 within row
    int it = g >> 3;                               // k-block (32 floats)
    int kg = g & 7;                                // float4 within block
    float4 v = *reinterpret_cast<const float4*>(&B[(size_t)n * DDIM + g * 4]);
    uint2 h, m, l;
    split3_f4(v, h, m, l);
    int pchunk = (kg >> 1) ^ ((n >> 1) & 3);
    size_t off = (size_t)n * 64 + pchunk * 16 + (kg & 1) * 8;
    size_t base = (size_t)it * 3 * B_LVL_BYTES;
    *reinterpret_cast<uint2*>(g_bpre + base + 0 * B_LVL_BYTES + off) = h;
    *reinterpret_cast<uint2*>(g_bpre + base + 1 * B_LVL_BYTES + off) = m;
    *reinterpret_cast<uint2*>(g_bpre + base + 2 * B_LVL_BYTES + off) = l;
}

// ---------------------------------------------------------------------------
// Fused main kernel: bf16x3 HMMA GEMM + sqrt-softplus + stable top-6.
// ---------------------------------------------------------------------------
__global__ __launch_bounds__(NTHREADS, 1) void gate_main(
    const float* __restrict__ A, const float* __restrict__ bias,
    float* __restrict__ out) {
    extern __shared__ char smem[];
    const int tid  = threadIdx.x;
    const int lane = tid & 31;
    const int wid  = tid >> 5;
    const int wm   = wid >> 2;          // 0..1
    const int wn   = wid & 3;           // 0..3
    const int mBase = blockIdx.x * BM;
    float* s_bias = reinterpret_cast<float*>(smem + SM_BIAS);

    if (tid < NEXP) s_bias[tid] = bias[tid];

    const int g = lane >> 3;            // ldmatrix lane group
    const int l7 = lane & 7;

    float acc[2][8][4];     // chunk accumulators
    float mst[2][8][4];     // master accumulators
#pragma unroll
    for (int i = 0; i < 2; i++)
#pragma unroll
        for (int j = 0; j < 8; j++)
#pragma unroll
            for (int c = 0; c < 4; c++) { acc[i][j][c] = 0.0f; mst[i][j][c] = 0.0f; }

    // A LDG task: (i,t) -> row = i*32 + t/8, kg = t&7
    const int arow[2] = {0 * 32 + (tid >> 3), 1 * 32 + (tid >> 3)};
    const int akg = tid & 7;

    // ---- prologue: stage 0 ----
    {
        char* st = smem + SM_STAGE;
        uint32_t sa = smem_u32(st);
        uint32_t stB = sa + B_OFF;
#pragma unroll
        for (int j = 0; j < 12; j++) {
            int idx = j * NTHREADS + tid;
            cpasync16(stB + idx * 16, g_bpre + (size_t)0 * 3 * B_LVL_BYTES + idx * 16);
        }
        asm volatile("cp.async.commit_group;" ::: "memory");
#pragma unroll
        for (int i = 0; i < 2; i++) {
            float4 v = *reinterpret_cast<const float4*>(
                &A[(size_t)(mBase + arow[i]) * DDIM + 0 * BK + akg * 4]);
            uint2 h, m, l;
            split3_f4(v, h, m, l);
            int lchunk = akg >> 1, half = (akg & 1) * 8;
            sts_u2(row64_addr(sa + 0 * A_LVL_BYTES, arow[i], lchunk) + half, h);
            sts_u2(row64_addr(sa + 1 * A_LVL_BYTES, arow[i], lchunk) + half, m);
            sts_u2(row64_addr(sa + 2 * A_LVL_BYTES, arow[i], lchunk) + half, l);
        }
        asm volatile("cp.async.wait_group 0;" ::: "memory");
        __syncthreads();
    }

#pragma unroll 1
    for (int it = 0; it < NIT; it++) {
        const uint32_t stage  = smem_u32(smem) + SM_STAGE + (it & 1) * STAGE_BYTES;
        const uint32_t nstage = smem_u32(smem) + SM_STAGE + ((it + 1) & 1) * STAGE_BYTES;

        float4 areg[2];
        if (it + 1 < NIT) {
            // B for next stage via cp.async
#pragma unroll
            for (int j = 0; j < 12; j++) {
                int idx = j * NTHREADS + tid;
                cpasync16(nstage + B_OFF + idx * 16,
                          g_bpre + (size_t)(it + 1) * 3 * B_LVL_BYTES + idx * 16);
            }
            asm volatile("cp.async.commit_group;" ::: "memory");
            // A for next stage into regs
#pragma unroll
            for (int i = 0; i < 2; i++)
                areg[i] = *reinterpret_cast<const float4*>(
                    &A[(size_t)(mBase + arow[i]) * DDIM + (it + 1) * BK + akg * 4]);
        }

        // ---- compute current stage: 2 k16 steps ----
#pragma unroll
        for (int ks = 0; ks < 2; ks++) {
            uint32_t a[2][3][4];
#pragma unroll
            for (int mf = 0; mf < 2; mf++) {
                int row = wm * 32 + mf * 16 + (g & 1) * 8 + l7;
                int lchunk = ks * 2 + (g >> 1);
#pragma unroll
                for (int L = 0; L < 3; L++)
                    ldsm4(a[mf][L], row64_addr(stage + L * A_LVL_BYTES, row, lchunk));
            }
            int rowb = wn * 64 + (g >> 1) * 8 + l7;
            int lchb = ks * 2 + (g & 1);
            // B level h: products ah*bh, am*bh, al*bh
#pragma unroll
            for (int nf2 = 0; nf2 < 4; nf2++) {
                uint32_t b[4];
                ldsm4(b, row64_addr(stage + B_OFF + 0 * B_LVL_BYTES, rowb + nf2 * 16, lchb));
#pragma unroll
                for (int mf = 0; mf < 2; mf++) {
                    mma_bf16(acc[mf][nf2 * 2 + 0], a[mf][0], b[0], b[1]);
                    mma_bf16(acc[mf][nf2 * 2 + 1], a[mf][0], b[2], b[3]);
                    mma_bf16(acc[mf][nf2 * 2 + 0], a[mf][1], b[0], b[1]);
                    mma_bf16(acc[mf][nf2 * 2 + 1], a[mf][1], b[2], b[3]);
                    mma_bf16(acc[mf][nf2 * 2 + 0], a[mf][2], b[0], b[1]);
                    mma_bf16(acc[mf][nf2 * 2 + 1], a[mf][2], b[2], b[3]);
                }
            }
            // B level m: products ah*bm, am*bm
#pragma unroll
            for (int nf2 = 0; nf2 < 4; nf2++) {
                uint32_t b[4];
                ldsm4(b, row64_addr(stage + B_OFF + 1 * B_LVL_BYTES, rowb + nf2 * 16, lchb));
#pragma unroll
                for (int mf = 0; mf < 2; mf++) {
                    mma_bf16(acc[mf][nf2 * 2 + 0], a[mf][0], b[0], b[1]);
                    mma_bf16(acc[mf][nf2 * 2 + 1], a[mf][0], b[2], b[3]);
                    mma_bf16(acc[mf][nf2 * 2 + 0], a[mf][1], b[0], b[1]);
                    mma_bf16(acc[mf][nf2 * 2 + 1], a[mf][1], b[2], b[3]);
                }
            }
            // B level l: product ah*bl
#pragma unroll
            for (int nf2 = 0; nf2 < 4; nf2++) {
                uint32_t b[4];
                ldsm4(b, row64_addr(stage + B_OFF + 2 * B_LVL_BYTES, rowb + nf2 * 16, lchb));
#pragma unroll
                for (int mf = 0; mf < 2; mf++) {
                    mma_bf16(acc[mf][nf2 * 2 + 0], a[mf][0], b[0], b[1]);
                    mma_bf16(acc[mf][nf2 * 2 + 1], a[mf][0], b[2], b[3]);
                }
            }
        }

        if (it + 1 < NIT) {
            // store next A stage
#pragma unroll
            for (int i = 0; i < 2; i++) {
                uint2 h, m, l;
                split3_f4(areg[i], h, m, l);
                int lchunk = akg >> 1, half = (akg & 1) * 8;
                sts_u2(row64_addr(nstage + 0 * A_LVL_BYTES, arow[i], lchunk) + half, h);
                sts_u2(row64_addr(nstage + 1 * A_LVL_BYTES, arow[i], lchunk) + half, m);
                sts_u2(row64_addr(nstage + 2 * A_LVL_BYTES, arow[i], lchunk) + half, l);
            }
        }

        // fold chunk into master every 8 iterations (K chunk = 256)
        if ((it & 7) == 7) {
#pragma unroll
            for (int i = 0; i < 2; i++)
#pragma unroll
                for (int j = 0; j < 8; j++)
#pragma unroll
                    for (int c = 0; c < 4; c++) {
                        mst[i][j][c] += acc[i][j][c];
                        acc[i][j][c] = 0.0f;
                    }
        }

        if (it + 1 < NIT)
            asm volatile("cp.async.wait_group 0;" ::: "memory");
        __syncthreads();
    }

    // ---- write scores to smem (overlay stages) ----
    float* sc = reinterpret_cast<float*>(smem + SM_SCORES);
#pragma unroll
    for (int mf = 0; mf < 2; mf++) {
#pragma unroll
        for (int nf = 0; nf < 8; nf++) {
            int m0 = wm * 32 + mf * 16 + (lane >> 2);
            int n0 = wn * 64 + nf * 8 + (lane & 3) * 2;
            *reinterpret_cast<float2*>(&sc[m0 * SSTR + n0]) =
                make_float2(mst[mf][nf][0], mst[mf][nf][1]);
            *reinterpret_cast<float2*>(&sc[(m0 + 8) * SSTR + n0]) =
                make_float2(mst[mf][nf][2], mst[mf][nf][3]);
        }
    }
    __syncthreads();

    // ---- top-6: 4 threads per row, each scans 64 experts, then merge ----
    {
        const int r = tid >> 2;     // row 0..63
        const int q = tid & 3;      // quarter
        float tb[KTOP], to_[KTOP];
        int ti[KTOP];
#pragma unroll
        for (int i = 0; i < KTOP; i++) { tb[i] = -1e30f; to_[i] = 0.0f; ti[i] = 0; }
#pragma unroll 4
        for (int j = 0; j < 64; j++) {
            int e = q * 64 + j;
            float z = sc[r * SSTR + e];
            float sp = fmaxf(z, 0.0f) + log1pf(expf(-fabsf(z)));
            float o = sqrtf(sp);
            ins6(o + s_bias[e], o, e, tb, to_, ti);
        }
        float* pb = reinterpret_cast<float*>(smem + SM_PB);
        float* po = reinterpret_cast<float*>(smem + SM_PO);
        int*   pi = reinterpret_cast<int*>(smem + SM_PI);
#pragma unroll
        for (int i = 0; i < KTOP; i++) {
            pb[(r * 4 + q) * KTOP + i] = tb[i];
            po[(r * 4 + q) * KTOP + i] = to_[i];
            pi[(r * 4 + q) * KTOP + i] = ti[i];
        }
        __syncthreads();

        if (q == 0) {
            float fb[KTOP], fo[KTOP];
            int fi[KTOP];
#pragma unroll
            for (int i = 0; i < KTOP; i++) { fb[i] = -1e30f; fo[i] = 0.0f; fi[i] = 0; }
#pragma unroll
            for (int q2 = 0; q2 < 4; q2++)
#pragma unroll
                for (int i = 0; i < KTOP; i++)
                    ins6(pb[(r * 4 + q2) * KTOP + i], po[(r * 4 + q2) * KTOP + i],
                         pi[(r * 4 + q2) * KTOP + i], fb, fo, fi);
            float sum = 0.0f;
#pragma unroll
            for (int i = 0; i < KTOP; i++) sum += fo[i];
            const float s = 1.5f / sum;
            const size_t row = (size_t)(mBase + r);
#pragma unroll
            for (int i = 0; i < KTOP; i++) {
                out[row * KTOP + i] = fo[i] * s;
                out[(size_t)N_ROWS * KTOP + row * KTOP + i] = (float)fi[i];
            }
        }
    }
}

extern "C" void kernel_launch(void* const* d_in, const int* in_sizes, int n_in,
                              void* d_out, int out_size) {
    const float* x      = (const float*)d_in[0];   // [N, D]
    const float* weight = (const float*)d_in[1];   // [E, D]
    const float* bias   = (const float*)d_in[2];   // [E]
    float* out = (float*)d_out;

    preconvert_B<<<(NEXP * DDIM / 4) / 256, 256>>>(weight);
    cudaFuncSetAttribute(gate_main, cudaFuncAttributeMaxDynamicSharedMemorySize, SMEM_TOTAL);
    gate_main<<<N_ROWS / BM, NTHREADS, SMEM_TOTAL>>>(x, bias, out);
}

// round 6
// speedup vs baseline: 6.6324x; 1.6050x over previous
#include <cuda_runtime.h>
#include <cuda_fp16.h>
#include <cstdint>
#include <math.h>

#define N_ROWS 16384
#define DDIM   4096
#define NEXP   256
#define KTOP   6

#define BM 32             // rows per CTA
#define BK 32             // k per stage (two k16 steps)
#define NIT (DDIM / BK)   // 128
#define NTHREADS 256      // 8 warps: 2 (m) x 4 (n), warp tile 16x64
#define LO_SCALE 2048.0f
#define LO_UNSCALE 4.8828125e-4f   // 2^-11

// ---- smem layout (dynamic) ----
// [0,1024): bias; stages at 1024 + s*36864
// stage: A_h 2K | A_l 2K | B_h 16K | B_l 16K = 36K
#define SM_BIAS    0
#define SM_STAGE   1024
#define STAGE_BYTES 36864
#define A_LVL_BYTES 2048
#define B_OFF      4096
#define B_LVL_BYTES 16384
#define SMEM_TOTAL (SM_STAGE + 2 * STAGE_BYTES)   // 74752

// scores overlay (after mainloop): stride 260 floats to dodge bank conflicts
#define SSTR 260
#define SM_SCORES  SM_STAGE
#define SM_PB (SM_SCORES + BM * SSTR * 4)         // partial biased [32][8][6]
#define SM_PO (SM_PB + BM * 8 * KTOP * 4)
#define SM_PI (SM_PO + BM * 8 * KTOP * 4)

// 4 MB pre-converted, pre-swizzled B: [it(128)][level(2)][n(256)][64B]
__device__ __align__(16) uint8_t g_bpre[(size_t)NIT * 2 * NEXP * 64];

// ---------------------------------------------------------------------------
static __device__ __forceinline__ uint32_t smem_u32(const void* p) {
    uint32_t a;
    asm("{ .reg .u64 t; cvta.to.shared.u64 t, %1; cvt.u32.u64 %0, t; }" : "=r"(a) : "l"(p));
    return a;
}

static __device__ __forceinline__ void sts_u2(uint32_t addr, uint2 v) {
    asm volatile("st.shared.v2.b32 [%0], {%1, %2};"
                 :: "r"(addr), "r"(v.x), "r"(v.y) : "memory");
}

static __device__ __forceinline__ uint32_t pack_h2(__half lo, __half hi) {
    return (uint32_t)__half_as_ushort(lo) | ((uint32_t)__half_as_ushort(hi) << 16);
}

// split fp32x4 into fp16 hi + fp16 lo*2^11 (lo pre-scaled into normal range)
static __device__ __forceinline__ void split2_f4(float4 v, uint2& h, uint2& l) {
    float in[4] = {v.x, v.y, v.z, v.w};
    __half hh[4], hl[4];
#pragma unroll
    for (int i = 0; i < 4; i++) {
        float a = in[i];
        hh[i] = __float2half_rn(a);
        float r = a - __half2float(hh[i]);
        hl[i] = __float2half_rn(r * LO_SCALE);
    }
    h = make_uint2(pack_h2(hh[0], hh[1]), pack_h2(hh[2], hh[3]));
    l = make_uint2(pack_h2(hl[0], hl[1]), pack_h2(hl[2], hl[3]));
}

static __device__ __forceinline__ void ldsm4(uint32_t* r, uint32_t addr) {
    asm volatile("ldmatrix.sync.aligned.m8n8.x4.shared.b16 {%0,%1,%2,%3}, [%4];"
                 : "=r"(r[0]), "=r"(r[1]), "=r"(r[2]), "=r"(r[3]) : "r"(addr));
}

static __device__ __forceinline__ void mma_f16(float* d, const uint32_t* a,
                                               uint32_t b0, uint32_t b1) {
    asm volatile(
        "mma.sync.aligned.m16n8k16.row.col.f32.f16.f16.f32 "
        "{%0,%1,%2,%3}, {%4,%5,%6,%7}, {%8,%9}, {%0,%1,%2,%3};"
        : "+f"(d[0]), "+f"(d[1]), "+f"(d[2]), "+f"(d[3])
        : "r"(a[0]), "r"(a[1]), "r"(a[2]), "r"(a[3]), "r"(b0), "r"(b1));
}

static __device__ __forceinline__ void cpasync16(uint32_t dst, const void* src) {
    asm volatile("cp.async.cg.shared.global [%0], [%1], 16;" :: "r"(dst), "l"(src) : "memory");
}

// 64B-row swizzle: physical 16B chunk = logical chunk ^ ((row>>1)&3)
static __device__ __forceinline__ uint32_t row64_addr(uint32_t base, int row, int lchunk) {
    return base + row * 64 + ((lchunk ^ ((row >> 1) & 3)) << 4);
}

// stable strict-> insertion into top-6 (earlier insert wins ties = lower index)
static __device__ __forceinline__ void ins6(float b, float o, int idx,
                                            float* tb, float* to_, int* ti) {
    if (b > tb[KTOP - 1]) {
        int p = KTOP - 1;
#pragma unroll
        for (int q = KTOP - 1; q > 0; q--) {
            if (b > tb[q - 1]) {
                tb[q] = tb[q - 1]; to_[q] = to_[q - 1]; ti[q] = ti[q - 1];
                p = q - 1;
            }
        }
        tb[p] = b; to_[p] = o; ti[p] = idx;
    }
}

// ---------------------------------------------------------------------------
// Pre-kernel: split B[256][4096] fp32 into fp16 hi + scaled lo, stored as the
// exact per-iteration smem stage image (pre-swizzled 64B rows).
// ---------------------------------------------------------------------------
__global__ __launch_bounds__(256) void preconvert_B(const float* __restrict__ B) {
    int t = blockIdx.x * 256 + threadIdx.x;        // one float4 each; 262144 total
    int n  = t >> 10;                              // row 0..255
    int g  = t & 1023;                             // float4 within row
    int it = g >> 3;                               // k-block (32 floats)
    int kg = g & 7;                                // float4 within block
    float4 v = *reinterpret_cast<const float4*>(&B[(size_t)n * DDIM + g * 4]);
    uint2 h, l;
    split2_f4(v, h, l);
    int pchunk = (kg >> 1) ^ ((n >> 1) & 3);
    size_t off = (size_t)n * 64 + pchunk * 16 + (kg & 1) * 8;
    size_t base = (size_t)it * 2 * B_LVL_BYTES;
    *reinterpret_cast<uint2*>(g_bpre + base + 0 * B_LVL_BYTES + off) = h;
    *reinterpret_cast<uint2*>(g_bpre + base + 1 * B_LVL_BYTES + off) = l;
}

// ---------------------------------------------------------------------------
// Fused main kernel: fp16x2 HMMA GEMM + sqrt-softplus + stable top-6.
// acc0 = hi*hi (chunk-folded into mst); acc1 = hi*lo + lo*hi (scaled 2^11,
// folded once at the end * 2^-11 so its rounding noise is divided by 2048).
// ---------------------------------------------------------------------------
__global__ __launch_bounds__(NTHREADS, 2) void gate_main(
    const float* __restrict__ A, const float* __restrict__ bias,
    float* __restrict__ out) {
    extern __shared__ char smem[];
    const int tid  = threadIdx.x;
    const int lane = tid & 31;
    const int wid  = tid >> 5;
    const int wm   = wid >> 2;          // 0..1
    const int wn   = wid & 3;           // 0..3
    const int mBase = blockIdx.x * BM;
    float* s_bias = reinterpret_cast<float*>(smem + SM_BIAS);

    if (tid < NEXP) s_bias[tid] = bias[tid];

    const int g = lane >> 3;            // ldmatrix lane group
    const int l7 = lane & 7;

    float acc0[8][4], acc1[8][4], mst[8][4];
#pragma unroll
    for (int j = 0; j < 8; j++)
#pragma unroll
        for (int c = 0; c < 4; c++) { acc0[j][c] = 0.0f; acc1[j][c] = 0.0f; mst[j][c] = 0.0f; }

    // A LDG task: one float4 per thread
    const int arow = tid >> 3;          // 0..31
    const int akg  = tid & 7;

    // ---- prologue: stage 0 ----
    {
        uint32_t sa = smem_u32(smem) + SM_STAGE;
#pragma unroll
        for (int j = 0; j < 8; j++) {
            int idx = j * NTHREADS + tid;
            cpasync16(sa + B_OFF + idx * 16, g_bpre + (size_t)0 * 2 * B_LVL_BYTES + idx * 16);
        }
        asm volatile("cp.async.commit_group;" ::: "memory");
        float4 v = *reinterpret_cast<const float4*>(
            &A[(size_t)(mBase + arow) * DDIM + 0 * BK + akg * 4]);
        uint2 h, l;
        split2_f4(v, h, l);
        int lchunk = akg >> 1, half = (akg & 1) * 8;
        sts_u2(row64_addr(sa + 0 * A_LVL_BYTES, arow, lchunk) + half, h);
        sts_u2(row64_addr(sa + 1 * A_LVL_BYTES, arow, lchunk) + half, l);
        asm volatile("cp.async.wait_group 0;" ::: "memory");
        __syncthreads();
    }

#pragma unroll 1
    for (int it = 0; it < NIT; it++) {
        const uint32_t stage  = smem_u32(smem) + SM_STAGE + (it & 1) * STAGE_BYTES;
        const uint32_t nstage = smem_u32(smem) + SM_STAGE + ((it + 1) & 1) * STAGE_BYTES;

        float4 areg;
        if (it + 1 < NIT) {
#pragma unroll
            for (int j = 0; j < 8; j++) {
                int idx = j * NTHREADS + tid;
                cpasync16(nstage + B_OFF + idx * 16,
                          g_bpre + (size_t)(it + 1) * 2 * B_LVL_BYTES + idx * 16);
            }
            asm volatile("cp.async.commit_group;" ::: "memory");
            areg = *reinterpret_cast<const float4*>(
                &A[(size_t)(mBase + arow) * DDIM + (it + 1) * BK + akg * 4]);
        }

        // ---- compute current stage: 2 k16 steps ----
#pragma unroll
        for (int ks = 0; ks < 2; ks++) {
            uint32_t ah[4], al[4];
            {
                int row = wm * 16 + (g & 1) * 8 + l7;
                int lchunk = ks * 2 + (g >> 1);
                ldsm4(ah, row64_addr(stage + 0 * A_LVL_BYTES, row, lchunk));
                ldsm4(al, row64_addr(stage + 1 * A_LVL_BYTES, row, lchunk));
            }
            int rowb0 = wn * 64 + (g >> 1) * 8 + l7;
            int lchb  = ks * 2 + (g & 1);
#pragma unroll
            for (int nf2 = 0; nf2 < 4; nf2++) {
                uint32_t bh[4], bl[4];
                ldsm4(bh, row64_addr(stage + B_OFF + 0 * B_LVL_BYTES, rowb0 + nf2 * 16, lchb));
                ldsm4(bl, row64_addr(stage + B_OFF + 1 * B_LVL_BYTES, rowb0 + nf2 * 16, lchb));
                mma_f16(acc0[nf2 * 2 + 0], ah, bh[0], bh[1]);
                mma_f16(acc0[nf2 * 2 + 1], ah, bh[2], bh[3]);
                mma_f16(acc1[nf2 * 2 + 0], ah, bl[0], bl[1]);
                mma_f16(acc1[nf2 * 2 + 1], ah, bl[2], bl[3]);
                mma_f16(acc1[nf2 * 2 + 0], al, bh[0], bh[1]);
                mma_f16(acc1[nf2 * 2 + 1], al, bh[2], bh[3]);
            }
        }

        if (it + 1 < NIT) {
            uint2 h, l;
            split2_f4(areg, h, l);
            int lchunk = akg >> 1, half = (akg & 1) * 8;
            sts_u2(row64_addr(nstage + 0 * A_LVL_BYTES, arow, lchunk) + half, h);
            sts_u2(row64_addr(nstage + 1 * A_LVL_BYTES, arow, lchunk) + half, l);
        }

        // fold hi*hi chunk into master every 8 iterations (K chunk = 256)
        if ((it & 7) == 7) {
#pragma unroll
            for (int j = 0; j < 8; j++)
#pragma unroll
                for (int c = 0; c < 4; c++) { mst[j][c] += acc0[j][c]; acc0[j][c] = 0.0f; }
        }

        if (it + 1 < NIT)
            asm volatile("cp.async.wait_group 0;" ::: "memory");
        __syncthreads();
    }

    // ---- write scores to smem (overlay stages): score = mst + acc1 * 2^-11 ----
    float* sc = reinterpret_cast<float*>(smem + SM_SCORES);
#pragma unroll
    for (int nf = 0; nf < 8; nf++) {
        int m0 = wm * 16 + (lane >> 2);
        int n0 = wn * 64 + nf * 8 + (lane & 3) * 2;
        float s0 = mst[nf][0] + acc1[nf][0] * LO_UNSCALE;
        float s1 = mst[nf][1] + acc1[nf][1] * LO_UNSCALE;
        float s2 = mst[nf][2] + acc1[nf][2] * LO_UNSCALE;
        float s3 = mst[nf][3] + acc1[nf][3] * LO_UNSCALE;
        *reinterpret_cast<float2*>(&sc[m0 * SSTR + n0]) = make_float2(s0, s1);
        *reinterpret_cast<float2*>(&sc[(m0 + 8) * SSTR + n0]) = make_float2(s2, s3);
    }
    __syncthreads();

    // ---- top-6: 8 threads per row, each scans 32 experts, then merge ----
    {
        const int r = tid >> 3;     // row 0..31
        const int q = tid & 7;      // eighth
        float tb[KTOP], to_[KTOP];
        int ti[KTOP];
#pragma unroll
        for (int i = 0; i < KTOP; i++) { tb[i] = -1e30f; to_[i] = 0.0f; ti[i] = 0; }
#pragma unroll 4
        for (int j = 0; j < 32; j++) {
            int e = q * 32 + j;
            float z = sc[r * SSTR + e];
            float sp = fmaxf(z, 0.0f) + log1pf(expf(-fabsf(z)));
            float o = sqrtf(sp);
            ins6(o + s_bias[e], o, e, tb, to_, ti);
        }
        float* pb = reinterpret_cast<float*>(smem + SM_PB);
        float* po = reinterpret_cast<float*>(smem + SM_PO);
        int*   pi = reinterpret_cast<int*>(smem + SM_PI);
#pragma unroll
        for (int i = 0; i < KTOP; i++) {
            pb[(r * 8 + q) * KTOP + i] = tb[i];
            po[(r * 8 + q) * KTOP + i] = to_[i];
            pi[(r * 8 + q) * KTOP + i] = ti[i];
        }
        __syncthreads();

        if (q == 0) {
            float fb[KTOP], fo[KTOP];
            int fi[KTOP];
#pragma unroll
            for (int i = 0; i < KTOP; i++) { fb[i] = -1e30f; fo[i] = 0.0f; fi[i] = 0; }
#pragma unroll
            for (int q2 = 0; q2 < 8; q2++)
#pragma unroll
                for (int i = 0; i < KTOP; i++)
                    ins6(pb[(r * 8 + q2) * KTOP + i], po[(r * 8 + q2) * KTOP + i],
                         pi[(r * 8 + q2) * KTOP + i], fb, fo, fi);
            float sum = 0.0f;
#pragma unroll
            for (int i = 0; i < KTOP; i++) sum += fo[i];
            const float s = 1.5f / sum;
            const size_t row = (size_t)(mBase + r);
#pragma unroll
            for (int i = 0; i < KTOP; i++) {
                out[row * KTOP + i] = fo[i] * s;
                out[(size_t)N_ROWS * KTOP + row * KTOP + i] = (float)fi[i];
            }
        }
    }
}

extern "C" void kernel_launch(void* const* d_in, const int* in_sizes, int n_in,
                              void* d_out, int out_size) {
    const float* x      = (const float*)d_in[0];   // [N, D]
    const float* weight = (const float*)d_in[1];   // [E, D]
    const float* bias   = (const float*)d_in[2];   // [E]
    float* out = (float*)d_out;

    preconvert_B<<<(NEXP * DDIM / 4) / 256, 256>>>(weight);
    cudaFuncSetAttribute(gate_main, cudaFuncAttributeMaxDynamicSharedMemorySize, SMEM_TOTAL);
    gate_main<<<N_ROWS / BM, NTHREADS, SMEM_TOTAL>>>(x, bias, out);
}